// round 16
// baseline (speedup 1.0000x reference)
#include <cuda_runtime.h>
#include <math.h>

#define HIDDEN   1024
#define WPB      8                    // tokens per hot block (1 warp each, same seq position)
#define THREADS  (WPB * 32)           // 256
#define SEQ      2048
#define NUM_FEATS 94
#define PROJ     256
#define NUM_TOKEN_ID 5
#define LN_EPS   1e-12f
#define FIX_BLOCKS 64                 // parallel fixup scan blocks (64*256 lanes)

// Warp-wide {sum, sumsq} butterfly reduction; every lane gets the totals.
__device__ __forceinline__ void warp_red2(float& s, float& sq) {
    #pragma unroll
    for (int o = 16; o > 0; o >>= 1) {
        s  += __shfl_xor_sync(0xffffffffu, s,  o);
        sq += __shfl_xor_sync(0xffffffffu, sq, o);
    }
}

// ===========================================================================
// Single kernel, block-level role split.
//   blockIdx.x <  FIX_BLOCKS : fixup — scan a 256-token slice (1 ballot
//                              iteration per warp), full MLP row for each
//                              active numeric token (rare). Sole writer of
//                              those rows. Cold path; spills are free.
//   blockIdx.x >= FIX_BLOCKS : hot path — block-per-POSITION. The 8 warps
//                              handle the 8 batch tokens sharing position s;
//                              Wpos[s]+Wtype[0] pre-summed into smem row P;
//                              ln_g/ln_b in smem. id/val loads hoisted above
//                              the fill barrier to overlap latency.
// smem union (12 KB): hot = {P, ln_g, ln_b}; fixup = {feats, h}.
// ===========================================================================
__global__ __launch_bounds__(THREADS, 6)
void blackhole_embed_kernel(const int*   __restrict__ ids,
                            const float* __restrict__ vals,
                            const int*   __restrict__ fmts,
                            const float* __restrict__ Wword,
                            const float* __restrict__ Wpos,
                            const float* __restrict__ Wtype,
                            const float* __restrict__ ln_g,
                            const float* __restrict__ ln_b,
                            const float* __restrict__ pw1,
                            const float* __restrict__ pb1,
                            const float* __restrict__ pw2,
                            const float* __restrict__ pb2,
                            const float* __restrict__ pln_g,
                            const float* __restrict__ pln_b,
                            float*       __restrict__ out,
                            int          n_tokens)
{
    const int warp = threadIdx.x >> 5;
    const int lane = threadIdx.x & 31;

    __shared__ __align__(16) float smbuf[3 * HIDDEN];    // 12 KB union

    if (blockIdx.x >= FIX_BLOCKS) {
        // ========== HOT PATH: block-per-position, warp-per-batch-token ==========
        const int s = blockIdx.x - FIX_BLOCKS;           // sequence position
        const int t = warp * SEQ + s;                    // batch = warp index

        // Hoisted: id/val in flight while the block fills smem.
        const int   id  = ids[t];
        const float val = vals[t];

        float* P_sm  = smbuf;                            // Wpos[s] + Wtype[0]
        float* lg_sm = smbuf + HIDDEN;
        float* lb_sm = smbuf + 2 * HIDDEN;

        // Cooperative one-time fill (Wpos row loaded ONCE for 8 tokens).
        {
            const int i = threadIdx.x;                   // 256 float4 per array
            float4 p = reinterpret_cast<const float4*>(Wpos)[(size_t)s * 256 + i];
            float4 q = reinterpret_cast<const float4*>(Wtype)[i];
            float4 r;
            r.x = p.x + q.x; r.y = p.y + q.y; r.z = p.z + q.z; r.w = p.w + q.w;
            reinterpret_cast<float4*>(P_sm)[i]  = r;
            reinterpret_cast<float4*>(lg_sm)[i] = reinterpret_cast<const float4*>(ln_g)[i];
            reinterpret_cast<float4*>(lb_sm)[i] = reinterpret_cast<const float4*>(ln_b)[i];
        }
        __syncthreads();

        // Active numeric token: the owning fixup block writes this row.
        if ((id == NUM_TOKEN_ID) && !isnan(val)) return;

        const float4* Ww = reinterpret_cast<const float4*>(Wword) + (size_t)id * 256;

        float4 x[8];
        #pragma unroll
        for (int j = 0; j < 8; j++) x[j] = Ww[j * 32 + lane];
        #pragma unroll
        for (int j = 0; j < 8; j++) {
            const float4 p = *reinterpret_cast<const float4*>(P_sm + j * 128 + lane * 4);
            x[j].x += p.x;
            x[j].y += p.y;
            x[j].z += p.z;
            x[j].w += p.w;
        }

        float sum = 0.f, sq = 0.f;
        #pragma unroll
        for (int j = 0; j < 8; j++) {
            sum += x[j].x + x[j].y + x[j].z + x[j].w;
            sq  += x[j].x * x[j].x + x[j].y * x[j].y + x[j].z * x[j].z + x[j].w * x[j].w;
        }
        warp_red2(sum, sq);
        const float mean = sum * (1.0f / 1024.0f);
        const float inv  = rsqrtf(sq * (1.0f / 1024.0f) - mean * mean + LN_EPS);

        float4* orow = reinterpret_cast<float4*>(out) + (size_t)t * 256;
        #pragma unroll
        for (int j = 0; j < 8; j++) {
            const float4 g = *reinterpret_cast<const float4*>(lg_sm + j * 128 + lane * 4);
            const float4 b = *reinterpret_cast<const float4*>(lb_sm + j * 128 + lane * 4);
            float4 o;
            o.x = (x[j].x - mean) * inv * g.x + b.x;
            o.y = (x[j].y - mean) * inv * g.y + b.y;
            o.z = (x[j].z - mean) * inv * g.z + b.z;
            o.w = (x[j].w - mean) * inv * g.w + b.w;
            __stcs(orow + j * 32 + lane, o);             // write-once: evict-first
        }
        return;
    }

    // ====================== FIXUP BLOCKS ======================
    // Each block scans a contiguous 256-token slice: warp w covers tokens
    // [slice + w*32, slice + w*32 + 32) in ONE ballot iteration.
    float* F = smbuf + warp * (NUM_FEATS + 2);                    // 8 x 96
    float* H = smbuf + WPB * (NUM_FEATS + 2) + warp * PROJ;       // 8 x 256

    const int base = blockIdx.x * THREADS + warp * 32;
    const int t_lane = base + lane;
    bool act = false;
    if (t_lane < n_tokens)
        act = (ids[t_lane] == NUM_TOKEN_ID) && !isnan(vals[t_lane]);
    unsigned m = __ballot_sync(0xffffffffu, act);

    while (m) {
        const int src = __ffs(m) - 1;
        m &= m - 1;
        const int t = base + src;
        const int s = t & (SEQ - 1);
        const float v32 = vals[t];
        const int   fmt = fmts[t];

        // ---- text embedding (id is NUM_TOKEN_ID by construction) ----
        const float4* Ww = reinterpret_cast<const float4*>(Wword) + (size_t)NUM_TOKEN_ID * 256;
        const float4* Wp = reinterpret_cast<const float4*>(Wpos)  + (size_t)s * 256;
        const float4* Wt = reinterpret_cast<const float4*>(Wtype);
        float4 x[8];
        #pragma unroll
        for (int j = 0; j < 8; j++) {
            float4 w = Ww[j * 32 + lane];
            float4 p = Wp[j * 32 + lane];
            float4 q = Wt[j * 32 + lane];
            x[j].x = w.x + p.x + q.x;
            x[j].y = w.y + p.y + q.y;
            x[j].z = w.z + p.z + q.z;
            x[j].w = w.w + p.w + q.w;
        }

        // ---- 94 numeric features (exact float64 semantics) ----
        {
            const double v  = (double)v32;
            const double av = fabs(v);
            const double fl = floor(av);
            for (int i = lane; i < NUM_FEATS; i += 32) {
                float f = 0.0f;
                if (i < 64) {
                    // signed int64 mask: (bits & (1<<63)) > 0 is always false
                    const long long bits = __double_as_longlong(v);
                    f = (i < 63 && ((bits >> i) & 1LL)) ? 1.0f : 0.0f;
                } else if (i < 74) {
                    int units = (int)fmin(fmax(fmod(fl, 10.0), 0.0), 9.0);
                    f = ((i - 64) == units) ? 1.0f : 0.0f;
                } else if (i < 84) {
                    int tens = (int)fmin(fmax(fmod(floor(fl / 10.0), 10.0), 0.0), 9.0);
                    f = ((i - 74) == tens) ? 1.0f : 0.0f;
                } else {
                    switch (i - 84) {
                        case 0: f = (float)log(av + 1e-6); break;
                        case 1: f = (v > 0.0) ? 1.0f : ((v < 0.0) ? -1.0f : 0.0f); break;
                        case 2: f = (av > 1e-6) ? (float)floor(log10(fmax(av, 1e-300))) : 0.0f; break;
                        case 3: f = (av == fl) ? 1.0f : 0.0f; break;
                        case 4: f = (v > 0.0) ? 1.0f : 0.0f; break;
                        case 5: f = (v == 0.0) ? 1.0f : 0.0f; break;
                        case 6: f = (v < 0.0) ? 1.0f : 0.0f; break;
                        case 7: {
                            bool pos_int = (v == floor(v)) && (v > 0.0);
                            double l2 = log2(fmax(v, 1.0));
                            f = (pos_int && (l2 == floor(l2))) ? 1.0f : 0.0f;
                        } break;
                        case 8: f = (fmt == 0) ? 1.0f : 0.0f; break;
                        case 9: f = (fmt == 1) ? 1.0f : 0.0f; break;
                    }
                }
                F[i] = f;
            }
        }
        __syncwarp();

        // ---- layer 1: [94] -> [256], exact GELU ----
        for (int j = 0; j < 8; j++) {
            const int col = j * 32 + lane;
            float acc = pb1[col];
            for (int k = 0; k < NUM_FEATS; k++)
                acc = fmaf(F[k], pw1[k * PROJ + col], acc);
            H[col] = 0.5f * acc * (1.0f + erff(acc * 0.70710678118654752f));
        }
        __syncwarp();

        // ---- layer 2: [256] -> [1024] (spills under cap; rare) ----
        float4 nacc[8];
        float sum = 0.f, sq = 0.f;
        for (int j = 0; j < 8; j++) {
            float4 acc = reinterpret_cast<const float4*>(pb2)[j * 32 + lane];
            for (int k = 0; k < PROJ; k++) {
                const float hk = H[k];
                const float4 wv =
                    reinterpret_cast<const float4*>(pw2 + (size_t)k * HIDDEN)[j * 32 + lane];
                acc.x = fmaf(hk, wv.x, acc.x);
                acc.y = fmaf(hk, wv.y, acc.y);
                acc.z = fmaf(hk, wv.z, acc.z);
                acc.w = fmaf(hk, wv.w, acc.w);
            }
            nacc[j] = acc;
            sum += acc.x + acc.y + acc.z + acc.w;
            sq  += acc.x * acc.x + acc.y * acc.y + acc.z * acc.z + acc.w * acc.w;
        }

        // ---- projection LayerNorm ----
        warp_red2(sum, sq);
        {
            const float mean = sum * (1.0f / 1024.0f);
            const float inv  = rsqrtf(sq * (1.0f / 1024.0f) - mean * mean + LN_EPS);
            for (int j = 0; j < 8; j++) {
                const float4 g = reinterpret_cast<const float4*>(pln_g)[j * 32 + lane];
                const float4 b = reinterpret_cast<const float4*>(pln_b)[j * 32 + lane];
                x[j].x += (nacc[j].x - mean) * inv * g.x + b.x;
                x[j].y += (nacc[j].y - mean) * inv * g.y + b.y;
                x[j].z += (nacc[j].z - mean) * inv * g.z + b.z;
                x[j].w += (nacc[j].w - mean) * inv * g.w + b.w;
            }
        }

        // ---- final LayerNorm + store ----
        sum = 0.f; sq = 0.f;
        #pragma unroll
        for (int j = 0; j < 8; j++) {
            sum += x[j].x + x[j].y + x[j].z + x[j].w;
            sq  += x[j].x * x[j].x + x[j].y * x[j].y + x[j].z * x[j].z + x[j].w * x[j].w;
        }
        warp_red2(sum, sq);
        const float mean = sum * (1.0f / 1024.0f);
        const float inv  = rsqrtf(sq * (1.0f / 1024.0f) - mean * mean + LN_EPS);

        float4* orow = reinterpret_cast<float4*>(out) + (size_t)t * 256;
        #pragma unroll
        for (int j = 0; j < 8; j++) {
            const float4 g = reinterpret_cast<const float4*>(ln_g)[j * 32 + lane];
            const float4 b = reinterpret_cast<const float4*>(ln_b)[j * 32 + lane];
            float4 o;
            o.x = (x[j].x - mean) * inv * g.x + b.x;
            o.y = (x[j].y - mean) * inv * g.y + b.y;
            o.z = (x[j].z - mean) * inv * g.z + b.z;
            o.w = (x[j].w - mean) * inv * g.w + b.w;
            orow[j * 32 + lane] = o;
        }
    }
}

extern "C" void kernel_launch(void* const* d_in, const int* in_sizes, int n_in,
                              void* d_out, int out_size)
{
    const int*   ids   = (const int*)  d_in[0];   // input_ids (int32 in harness)
    const float* vals  = (const float*)d_in[1];
    const int*   fmts  = (const int*)  d_in[2];
    const float* Wword = (const float*)d_in[3];   // [50257,1024]
    const float* Wpos  = (const float*)d_in[4];   // [4096,1024]
    const float* Wtype = (const float*)d_in[5];   // [2,1024]
    const float* ln_g  = (const float*)d_in[6];
    const float* ln_b  = (const float*)d_in[7];
    const float* pw1   = (const float*)d_in[8];   // [94,256]
    const float* pb1   = (const float*)d_in[9];
    const float* pw2   = (const float*)d_in[10];  // [256,1024]
    const float* pb2   = (const float*)d_in[11];
    const float* plng  = (const float*)d_in[12];
    const float* plnb  = (const float*)d_in[13];
    float*       out   = (float*)d_out;

    const int n_tokens = in_sizes[0];             // B*S = 16384 (B=8, S=2048)
    // Hot blocks: one per sequence position. Fixup: 64 blocks cover all tokens.
    const int grid = FIX_BLOCKS + SEQ;
    blackhole_embed_kernel<<<grid, THREADS>>>(
        ids, vals, fmts, Wword, Wpos, Wtype, ln_g, ln_b,
        pw1, pb1, pw2, pb2, plng, plnb, out, n_tokens);
}

// round 17
// speedup vs baseline: 1.1794x; 1.1794x over previous
#include <cuda_runtime.h>
#include <math.h>

#define HIDDEN   1024
#define WPB      8                    // tokens per hot block (1 warp each, same seq position)
#define THREADS  (WPB * 32)           // 256
#define SEQ      2048
#define NUM_FEATS 94
#define PROJ     256
#define NUM_TOKEN_ID 5
#define LN_EPS   1e-12f
#define FIX_BLOCKS 64                 // parallel fixup scan blocks (64*256 lanes)

// Warp-wide {sum, sumsq} butterfly reduction; every lane gets the totals.
__device__ __forceinline__ void warp_red2(float& s, float& sq) {
    #pragma unroll
    for (int o = 16; o > 0; o >>= 1) {
        s  += __shfl_xor_sync(0xffffffffu, s,  o);
        sq += __shfl_xor_sync(0xffffffffu, sq, o);
    }
}

// ===========================================================================
// Single kernel, block-level role split.
//   blockIdx.x <  FIX_BLOCKS : fixup — scan a 256-token slice (1 ballot
//                              iteration per warp), full MLP row for each
//                              active numeric token (rare). Sole writer of
//                              those rows. Cold path; spills are free.
//   blockIdx.x >= FIX_BLOCKS : hot path — block-per-POSITION. The 8 warps
//                              handle the 8 batch tokens sharing position s.
//                              CRITICAL-PATH ORDER: the 8 Wword gathers are
//                              issued FIRST, then the cooperative fill of
//                              {Wpos[s]+Wtype[0], ln_g, ln_b} overlaps their
//                              DRAM latency, then the barrier.
// smem union (12 KB): hot = {P, ln_g, ln_b}; fixup = {feats, h}.
// ===========================================================================
__global__ __launch_bounds__(THREADS, 5)
void blackhole_embed_kernel(const int*   __restrict__ ids,
                            const float* __restrict__ vals,
                            const int*   __restrict__ fmts,
                            const float* __restrict__ Wword,
                            const float* __restrict__ Wpos,
                            const float* __restrict__ Wtype,
                            const float* __restrict__ ln_g,
                            const float* __restrict__ ln_b,
                            const float* __restrict__ pw1,
                            const float* __restrict__ pb1,
                            const float* __restrict__ pw2,
                            const float* __restrict__ pb2,
                            const float* __restrict__ pln_g,
                            const float* __restrict__ pln_b,
                            float*       __restrict__ out,
                            int          n_tokens)
{
    const int warp = threadIdx.x >> 5;
    const int lane = threadIdx.x & 31;

    __shared__ __align__(16) float smbuf[3 * HIDDEN];    // 12 KB union

    if (blockIdx.x >= FIX_BLOCKS) {
        // ========== HOT PATH: block-per-position, warp-per-batch-token ==========
        const int s = blockIdx.x - FIX_BLOCKS;           // sequence position
        const int t = warp * SEQ + s;                    // batch = warp index

        const int   id  = ids[t];
        const float val = vals[t];

        // 1) Issue the 8 deep gathers FIRST — they are the long pole.
        const float4* Ww = reinterpret_cast<const float4*>(Wword) + (size_t)id * 256;
        float4 x[8];
        #pragma unroll
        for (int j = 0; j < 8; j++) x[j] = Ww[j * 32 + lane];

        // 2) Cooperative fill overlaps the gather latency.
        float* P_sm  = smbuf;                            // Wpos[s] + Wtype[0]
        float* lg_sm = smbuf + HIDDEN;
        float* lb_sm = smbuf + 2 * HIDDEN;
        {
            const int i = threadIdx.x;                   // 256 float4 per array
            float4 p = reinterpret_cast<const float4*>(Wpos)[(size_t)s * 256 + i];
            float4 q = reinterpret_cast<const float4*>(Wtype)[i];
            float4 r;
            r.x = p.x + q.x; r.y = p.y + q.y; r.z = p.z + q.z; r.w = p.w + q.w;
            reinterpret_cast<float4*>(P_sm)[i]  = r;
            reinterpret_cast<float4*>(lg_sm)[i] = reinterpret_cast<const float4*>(ln_g)[i];
            reinterpret_cast<float4*>(lb_sm)[i] = reinterpret_cast<const float4*>(ln_b)[i];
        }
        __syncthreads();

        // Active numeric token: the owning fixup block writes this row.
        if ((id == NUM_TOKEN_ID) && !isnan(val)) return;

        #pragma unroll
        for (int j = 0; j < 8; j++) {
            const float4 p = *reinterpret_cast<const float4*>(P_sm + j * 128 + lane * 4);
            x[j].x += p.x;
            x[j].y += p.y;
            x[j].z += p.z;
            x[j].w += p.w;
        }

        float sum = 0.f, sq = 0.f;
        #pragma unroll
        for (int j = 0; j < 8; j++) {
            sum += x[j].x + x[j].y + x[j].z + x[j].w;
            sq  += x[j].x * x[j].x + x[j].y * x[j].y + x[j].z * x[j].z + x[j].w * x[j].w;
        }
        warp_red2(sum, sq);
        const float mean = sum * (1.0f / 1024.0f);
        const float inv  = rsqrtf(sq * (1.0f / 1024.0f) - mean * mean + LN_EPS);

        float4* orow = reinterpret_cast<float4*>(out) + (size_t)t * 256;
        #pragma unroll
        for (int j = 0; j < 8; j++) {
            const float4 g = *reinterpret_cast<const float4*>(lg_sm + j * 128 + lane * 4);
            const float4 b = *reinterpret_cast<const float4*>(lb_sm + j * 128 + lane * 4);
            float4 o;
            o.x = (x[j].x - mean) * inv * g.x + b.x;
            o.y = (x[j].y - mean) * inv * g.y + b.y;
            o.z = (x[j].z - mean) * inv * g.z + b.z;
            o.w = (x[j].w - mean) * inv * g.w + b.w;
            __stcs(orow + j * 32 + lane, o);             // write-once: evict-first
        }
        return;
    }

    // ====================== FIXUP BLOCKS ======================
    // Each block scans a contiguous 256-token slice: warp w covers tokens
    // [slice + w*32, slice + w*32 + 32) in ONE ballot iteration.
    float* F = smbuf + warp * (NUM_FEATS + 2);                    // 8 x 96
    float* H = smbuf + WPB * (NUM_FEATS + 2) + warp * PROJ;       // 8 x 256

    const int base = blockIdx.x * THREADS + warp * 32;
    const int t_lane = base + lane;
    bool act = false;
    if (t_lane < n_tokens)
        act = (ids[t_lane] == NUM_TOKEN_ID) && !isnan(vals[t_lane]);
    unsigned m = __ballot_sync(0xffffffffu, act);

    while (m) {
        const int src = __ffs(m) - 1;
        m &= m - 1;
        const int t = base + src;
        const int s = t & (SEQ - 1);
        const float v32 = vals[t];
        const int   fmt = fmts[t];

        // ---- text embedding (id is NUM_TOKEN_ID by construction) ----
        const float4* Ww = reinterpret_cast<const float4*>(Wword) + (size_t)NUM_TOKEN_ID * 256;
        const float4* Wp = reinterpret_cast<const float4*>(Wpos)  + (size_t)s * 256;
        const float4* Wt = reinterpret_cast<const float4*>(Wtype);
        float4 x[8];
        #pragma unroll
        for (int j = 0; j < 8; j++) {
            float4 w = Ww[j * 32 + lane];
            float4 p = Wp[j * 32 + lane];
            float4 q = Wt[j * 32 + lane];
            x[j].x = w.x + p.x + q.x;
            x[j].y = w.y + p.y + q.y;
            x[j].z = w.z + p.z + q.z;
            x[j].w = w.w + p.w + q.w;
        }

        // ---- 94 numeric features (exact float64 semantics) ----
        {
            const double v  = (double)v32;
            const double av = fabs(v);
            const double fl = floor(av);
            for (int i = lane; i < NUM_FEATS; i += 32) {
                float f = 0.0f;
                if (i < 64) {
                    // signed int64 mask: (bits & (1<<63)) > 0 is always false
                    const long long bits = __double_as_longlong(v);
                    f = (i < 63 && ((bits >> i) & 1LL)) ? 1.0f : 0.0f;
                } else if (i < 74) {
                    int units = (int)fmin(fmax(fmod(fl, 10.0), 0.0), 9.0);
                    f = ((i - 64) == units) ? 1.0f : 0.0f;
                } else if (i < 84) {
                    int tens = (int)fmin(fmax(fmod(floor(fl / 10.0), 10.0), 0.0), 9.0);
                    f = ((i - 74) == tens) ? 1.0f : 0.0f;
                } else {
                    switch (i - 84) {
                        case 0: f = (float)log(av + 1e-6); break;
                        case 1: f = (v > 0.0) ? 1.0f : ((v < 0.0) ? -1.0f : 0.0f); break;
                        case 2: f = (av > 1e-6) ? (float)floor(log10(fmax(av, 1e-300))) : 0.0f; break;
                        case 3: f = (av == fl) ? 1.0f : 0.0f; break;
                        case 4: f = (v > 0.0) ? 1.0f : 0.0f; break;
                        case 5: f = (v == 0.0) ? 1.0f : 0.0f; break;
                        case 6: f = (v < 0.0) ? 1.0f : 0.0f; break;
                        case 7: {
                            bool pos_int = (v == floor(v)) && (v > 0.0);
                            double l2 = log2(fmax(v, 1.0));
                            f = (pos_int && (l2 == floor(l2))) ? 1.0f : 0.0f;
                        } break;
                        case 8: f = (fmt == 0) ? 1.0f : 0.0f; break;
                        case 9: f = (fmt == 1) ? 1.0f : 0.0f; break;
                    }
                }
                F[i] = f;
            }
        }
        __syncwarp();

        // ---- layer 1: [94] -> [256], exact GELU ----
        for (int j = 0; j < 8; j++) {
            const int col = j * 32 + lane;
            float acc = pb1[col];
            for (int k = 0; k < NUM_FEATS; k++)
                acc = fmaf(F[k], pw1[k * PROJ + col], acc);
            H[col] = 0.5f * acc * (1.0f + erff(acc * 0.70710678118654752f));
        }
        __syncwarp();

        // ---- layer 2: [256] -> [1024] (spills under cap; rare) ----
        float4 nacc[8];
        float sum = 0.f, sq = 0.f;
        for (int j = 0; j < 8; j++) {
            float4 acc = reinterpret_cast<const float4*>(pb2)[j * 32 + lane];
            for (int k = 0; k < PROJ; k++) {
                const float hk = H[k];
                const float4 wv =
                    reinterpret_cast<const float4*>(pw2 + (size_t)k * HIDDEN)[j * 32 + lane];
                acc.x = fmaf(hk, wv.x, acc.x);
                acc.y = fmaf(hk, wv.y, acc.y);
                acc.z = fmaf(hk, wv.z, acc.z);
                acc.w = fmaf(hk, wv.w, acc.w);
            }
            nacc[j] = acc;
            sum += acc.x + acc.y + acc.z + acc.w;
            sq  += acc.x * acc.x + acc.y * acc.y + acc.z * acc.z + acc.w * acc.w;
        }

        // ---- projection LayerNorm ----
        warp_red2(sum, sq);
        {
            const float mean = sum * (1.0f / 1024.0f);
            const float inv  = rsqrtf(sq * (1.0f / 1024.0f) - mean * mean + LN_EPS);
            for (int j = 0; j < 8; j++) {
                const float4 g = reinterpret_cast<const float4*>(pln_g)[j * 32 + lane];
                const float4 b = reinterpret_cast<const float4*>(pln_b)[j * 32 + lane];
                x[j].x += (nacc[j].x - mean) * inv * g.x + b.x;
                x[j].y += (nacc[j].y - mean) * inv * g.y + b.y;
                x[j].z += (nacc[j].z - mean) * inv * g.z + b.z;
                x[j].w += (nacc[j].w - mean) * inv * g.w + b.w;
            }
        }

        // ---- final LayerNorm + store ----
        sum = 0.f; sq = 0.f;
        #pragma unroll
        for (int j = 0; j < 8; j++) {
            sum += x[j].x + x[j].y + x[j].z + x[j].w;
            sq  += x[j].x * x[j].x + x[j].y * x[j].y + x[j].z * x[j].z + x[j].w * x[j].w;
        }
        warp_red2(sum, sq);
        const float mean = sum * (1.0f / 1024.0f);
        const float inv  = rsqrtf(sq * (1.0f / 1024.0f) - mean * mean + LN_EPS);

        float4* orow = reinterpret_cast<float4*>(out) + (size_t)t * 256;
        #pragma unroll
        for (int j = 0; j < 8; j++) {
            const float4 g = reinterpret_cast<const float4*>(ln_g)[j * 32 + lane];
            const float4 b = reinterpret_cast<const float4*>(ln_b)[j * 32 + lane];
            float4 o;
            o.x = (x[j].x - mean) * inv * g.x + b.x;
            o.y = (x[j].y - mean) * inv * g.y + b.y;
            o.z = (x[j].z - mean) * inv * g.z + b.z;
            o.w = (x[j].w - mean) * inv * g.w + b.w;
            orow[j * 32 + lane] = o;
        }
    }
}

extern "C" void kernel_launch(void* const* d_in, const int* in_sizes, int n_in,
                              void* d_out, int out_size)
{
    const int*   ids   = (const int*)  d_in[0];   // input_ids (int32 in harness)
    const float* vals  = (const float*)d_in[1];
    const int*   fmts  = (const int*)  d_in[2];
    const float* Wword = (const float*)d_in[3];   // [50257,1024]
    const float* Wpos  = (const float*)d_in[4];   // [4096,1024]
    const float* Wtype = (const float*)d_in[5];   // [2,1024]
    const float* ln_g  = (const float*)d_in[6];
    const float* ln_b  = (const float*)d_in[7];
    const float* pw1   = (const float*)d_in[8];   // [94,256]
    const float* pb1   = (const float*)d_in[9];
    const float* pw2   = (const float*)d_in[10];  // [256,1024]
    const float* pb2   = (const float*)d_in[11];
    const float* plng  = (const float*)d_in[12];
    const float* plnb  = (const float*)d_in[13];
    float*       out   = (float*)d_out;

    const int n_tokens = in_sizes[0];             // B*S = 16384 (B=8, S=2048)
    // Hot blocks: one per sequence position. Fixup: 64 blocks cover all tokens.
    const int grid = FIX_BLOCKS + SEQ;
    blackhole_embed_kernel<<<grid, THREADS>>>(
        ids, vals, fmts, Wword, Wpos, Wtype, ln_g, ln_b,
        pw1, pb1, pw2, pb2, plng, plnb, out, n_tokens);
}